// round 6
// baseline (speedup 1.0000x reference)
#include <cuda_runtime.h>
#include <cuda_bf16.h>
#include <math.h>

typedef unsigned int u32;
typedef unsigned long long u64;

#define NN 10000
#define NE 50000
#define IN_CH 32
#define EIN 16
#define GIN 8
#define HID 64
#define NG 64
#define EPS_BN 1e-5f

#define NODE_G 68     // source nodes per fused CTA  (148 CTAs = 1 wave)
#define MPAD 80       // mma M padding (5 x 16)
#define ECAP 400      // edge chunk capacity per CTA

// ---------------- device scratch ----------------
__device__ __align__(16) __nv_bfloat16 g_Wbf[8192 * 192]; // split W2: [j=c*64+o][k'=192] hi|lo|hi
__device__ float g_Ht [(size_t)128 * NE];  // H transposed, perm-ordered: [c][p]
__device__ float g_xA[NN * HID];
__device__ float g_xB[NN * HID];
__device__ float g_agg[NN * HID];
__device__ float g_xb [NN * HID];
__device__ int   g_cnt[NN];
__device__ int   g_off[NN + 1];
__device__ int   g_cur[NN];
__device__ int   g_perm[NE];
__device__ int   g_psrc[NE];
__device__ int   g_pdst[NE];
__device__ float g_bnsum[HID];
__device__ float g_bnsq [HID];
__device__ float g_pool[NG * HID];

// ---------------- PTX helpers (sm_80+ baseline) ----------------
__device__ __forceinline__ u32 smem_u32(const void* p) {
    u32 a;
    asm("{ .reg .u64 t; cvta.to.shared.u64 t, %1; cvt.u32.u64 %0, t; }" : "=r"(a) : "l"(p));
    return a;
}
__device__ __forceinline__ void ldsm_x4(u32& r0, u32& r1, u32& r2, u32& r3, u32 addr) {
    asm volatile("ldmatrix.sync.aligned.m8n8.x4.shared.b16 {%0,%1,%2,%3}, [%4];"
                 : "=r"(r0), "=r"(r1), "=r"(r2), "=r"(r3) : "r"(addr));
}
__device__ __forceinline__ void ldsm_x2(u32& r0, u32& r1, u32 addr) {
    asm volatile("ldmatrix.sync.aligned.m8n8.x2.shared.b16 {%0,%1}, [%2];"
                 : "=r"(r0), "=r"(r1) : "r"(addr));
}
__device__ __forceinline__ void mma16816(float* c, const u32* a, const u32* b) {
    asm volatile(
        "mma.sync.aligned.m16n8k16.row.col.f32.bf16.bf16.f32 "
        "{%0,%1,%2,%3}, {%4,%5,%6,%7}, {%8,%9}, {%0,%1,%2,%3};"
        : "+f"(c[0]), "+f"(c[1]), "+f"(c[2]), "+f"(c[3])
        : "r"(a[0]), "r"(a[1]), "r"(a[2]), "r"(a[3]), "r"(b[0]), "r"(b[1]));
}

// ---------------- CSR build ----------------
__global__ void k_zero_cnt() {
    int i = blockIdx.x * blockDim.x + threadIdx.x;
    if (i < NN) g_cnt[i] = 0;
}
__global__ void k_count(const int* __restrict__ src) {
    int e = blockIdx.x * blockDim.x + threadIdx.x;
    if (e < NE) atomicAdd(&g_cnt[src[e]], 1);
}
__global__ void k_scan() {
    __shared__ int part[1024];
    int t = threadIdx.x;
    const int CH = (NN + 1023) / 1024;
    int base = t * CH;
    int s = 0;
    for (int i = 0; i < CH; i++) {
        int idx = base + i;
        if (idx < NN) s += g_cnt[idx];
    }
    part[t] = s;
    __syncthreads();
    for (int d = 1; d < 1024; d <<= 1) {
        int v = (t >= d) ? part[t - d] : 0;
        __syncthreads();
        part[t] += v;
        __syncthreads();
    }
    int pre = (t == 0) ? 0 : part[t - 1];
    for (int i = 0; i < CH; i++) {
        int idx = base + i;
        if (idx < NN) {
            g_off[idx] = pre;
            g_cur[idx] = pre;
            pre += g_cnt[idx];
        }
    }
    if (t == 1023) g_off[NN] = part[1023];
}
__global__ void k_scatter(const int* __restrict__ src, const int* __restrict__ dst) {
    int e = blockIdx.x * blockDim.x + threadIdx.x;
    if (e < NE) {
        int s = src[e];
        int p = atomicAdd(&g_cur[s], 1);
        g_perm[p] = e;
        g_psrc[p] = s;
        g_pdst[p] = dst[e];
    }
}

// ---------------- W2 split+transpose: g_Wbf[j][k'], blocks [hi | lo | hi] ----------------
__global__ void k_wsplit(const float* __restrict__ w2, int K) {
    int p = blockIdx.x * blockDim.x + threadIdx.x;
    if (p >= 8192 * 192) return;
    int n = p / 192, j = p - n * 192;
    int b = j >> 6, k = j & 63;
    int c = n >> 6, o = n & 63;
    float v = (k < K) ? w2[(size_t)c * (K * 64) + k * 64 + o] : 0.f;
    __nv_bfloat16 hi = __float2bfloat16(v);
    __nv_bfloat16 outv = hi;
    if (b == 1) outv = __float2bfloat16(v - __bfloat162float(hi));
    g_Wbf[p] = outv;
}

// ---------------- edge hidden, transposed + perm-ordered: g_Ht[c][p] ----------------
#define EPB 32
__global__ void k_edge_h(const float* __restrict__ ea,
                         const float* __restrict__ w1,
                         const float* __restrict__ b1) {
    __shared__ float ws[EIN * 128];
    __shared__ float eas[EPB][17];
    __shared__ int   es[EPB];
    __shared__ float Hs[128][EPB + 1];
    int t = threadIdx.x;   // 128
    int p0 = blockIdx.x * EPB;
    int pe = min(EPB, NE - p0);
    for (int idx = t; idx < EIN * 128; idx += 128) ws[idx] = w1[idx];
    if (t < pe) es[t] = g_perm[p0 + t];
    __syncthreads();
    for (int idx = t; idx < pe * EIN; idx += 128) {
        int ei = idx >> 4, i = idx & 15;
        eas[ei][i] = ea[(size_t)es[ei] * EIN + i];
    }
    __syncthreads();
    int c = t;
    float b = b1[c];
    for (int ei = 0; ei < pe; ei++) {
        float s = b;
#pragma unroll
        for (int i = 0; i < EIN; i++) s += eas[ei][i] * ws[i * 128 + c];
        Hs[c][ei] = fmaxf(s, 0.f);
    }
    __syncthreads();
    for (int idx = t; idx < 128 * EPB; idx += 128) {
        int cc = idx >> 5, ei = idx & 31;
        if (ei < pe) g_Ht[(size_t)cc * NE + p0 + ei] = Hs[cc][ei];
    }
}

// ---------------- node pre: agg = x@root + bias ; xb = x@b2resh ----------------
__global__ void k_node_pre(const float* __restrict__ x, int C,
                           const float* __restrict__ root,
                           const float* __restrict__ bias,
                           const float* __restrict__ b2) {
    __shared__ float xs[4][64];
    __shared__ float rs[64 * 64];
    __shared__ float b2s[64 * 64];
    int t = threadIdx.x;
    int o = t & 63, s = t >> 6;
    for (int i = t; i < C * 64; i += 256) { rs[i] = root[i]; b2s[i] = b2[i]; }
    int n = blockIdx.x * 4 + s;
    if (n < NN) {
        for (int k = o; k < C; k += 64) xs[s][k] = x[(size_t)n * C + k];
    }
    __syncthreads();
    if (n < NN) {
        float a = bias[o], xbv = 0.f;
        for (int k = 0; k < C; k++) {
            float xv = xs[s][k];
            a   += xv * rs [k * 64 + o];
            xbv += xv * b2s[k * 64 + o];
        }
        g_agg[n * 64 + o] = a;
        g_xb [n * 64 + o] = xbv;
    }
}

// ---------------- FUSED: per-CTA Q tiles (mma) + edge messages, no Q in DRAM ----------------
// SMEM layout (bytes):
//   As   [MPAD x 200] bf16  @ 0        (32000)
//   Bs   [128  x 200] bf16  @ 32000    (51200)
//   Qs   [MPAD x 130] f32   @ 83200    (41600)
//   macc [ECAP x 64 ] f32   @ 124800   (102400)
//   sl   [ECAP] int         @ 227200   (1600)
#define FS_B 32000
#define FS_Q 83200
#define FS_M 124800
#define FS_SL 227200
#define FS_TOTAL 228800

__global__ void __launch_bounds__(256, 1) k_fused(const float* __restrict__ X, int K) {
    extern __shared__ char smem[];
    __nv_bfloat16* As = (__nv_bfloat16*)smem;
    __nv_bfloat16* Bs = (__nv_bfloat16*)(smem + FS_B);
    float* Qs   = (float*)(smem + FS_Q);
    float* macc = (float*)(smem + FS_M);
    int*   sl   = (int*)(smem + FS_SL);
    int t = threadIdx.x, wid = t >> 5, lane = t & 31;
    int n0 = blockIdx.x * NODE_G;

    // ---- A' fill: [hi | hi | lo], rows >= NODE_G or k >= K zeroed ----
    {
        u32* Au = (u32*)As;
        for (int idx = t; idx < MPAD * 96; idx += 256) {
            int r = idx / 96, pcp = idx - r * 96;
            int j = pcp * 2, b = j >> 6, k = j & 63;
            int n = n0 + r;
            float v0 = 0.f, v1 = 0.f;
            if (r < NODE_G && n < NN && k < K) {
                v0 = X[(size_t)n * K + k];
                if (k + 1 < K) v1 = X[(size_t)n * K + k + 1];
            }
            __nv_bfloat16 h0 = __float2bfloat16(v0);
            __nv_bfloat16 h1 = __float2bfloat16(v1);
            u32 pk;
            if (b == 2) {
                __nv_bfloat16 l0 = __float2bfloat16(v0 - __bfloat162float(h0));
                __nv_bfloat16 l1 = __float2bfloat16(v1 - __bfloat162float(h1));
                pk = (u32)__bfloat16_as_ushort(l0) | ((u32)__bfloat16_as_ushort(l1) << 16);
            } else {
                pk = (u32)__bfloat16_as_ushort(h0) | ((u32)__bfloat16_as_ushort(h1) << 16);
            }
            Au[r * 100 + pcp] = pk;
        }
    }

    int nend = n0 + NODE_G; if (nend > NN) nend = NN;
    int p0 = g_off[n0];
    int p1 = g_off[nend];
    __syncthreads();

    const uint4* W4 = (const uint4*)g_Wbf;
    u32 a_base = smem_u32(As);
    u32 b_base = smem_u32(Bs);

    for (int pc0 = p0; pc0 < p1; pc0 += ECAP) {
        int ce = min(ECAP, p1 - pc0);
        for (int i = t; i < ce; i += 256) sl[i] = g_psrc[pc0 + i] - n0;
        {
            float4* m4 = (float4*)macc;
            for (int i = t; i < ce * 16; i += 256) m4[i] = make_float4(0.f, 0.f, 0.f, 0.f);
        }
        __syncthreads();

        for (int cb = 0; cb < 64; cb++) {
            // ---- B tile: 128 j-rows x 192 k' ----
            {
                uint4* B4 = (uint4*)Bs;
                for (int idx = t; idx < 128 * 24; idx += 256) {
                    int r = idx / 24, q = idx - r * 24;
                    B4[r * 25 + q] = W4[(size_t)(cb * 128 + r) * 24 + q];
                }
            }
            __syncthreads();
            // ---- mma: 20 warp-tiles of 16x32 ----
            for (int wt = wid; wt < 20; wt += 8) {
                int mi = wt % 5, ni = wt / 5;
                int wm = mi * 16, wn = ni * 32;
                float acc[4][4];
#pragma unroll
                for (int j = 0; j < 4; j++)
#pragma unroll
                    for (int q = 0; q < 4; q++) acc[j][q] = 0.f;
#pragma unroll
                for (int ks = 0; ks < 12; ks++) {
                    int k0 = ks * 16;
                    u32 a[4];
                    u32 addrA = a_base + (u32)(((wm + (lane & 15)) * 200 +
                                                 k0 + ((lane >> 4) << 3)) * 2);
                    ldsm_x4(a[0], a[1], a[2], a[3], addrA);
                    u32 b[4][2];
#pragma unroll
                    for (int j = 0; j < 4; j++) {
                        u32 addrB = b_base + (u32)(((wn + j * 8 + (lane & 7)) * 200 +
                                                     k0 + ((lane >> 3) & 1) * 8) * 2);
                        ldsm_x2(b[j][0], b[j][1], addrB);
                    }
#pragma unroll
                    for (int j = 0; j < 4; j++) mma16816(acc[j], a, b[j]);
                }
                int m0 = wm + (lane >> 2);
#pragma unroll
                for (int j = 0; j < 4; j++) {
                    int col = wn + j * 8 + (lane & 3) * 2;
                    *(float2*)&Qs[m0 * 130 + col]       = make_float2(acc[j][0], acc[j][1]);
                    *(float2*)&Qs[(m0 + 8) * 130 + col] = make_float2(acc[j][2], acc[j][3]);
                }
            }
            __syncthreads();
            // ---- edge phase: warp = one edge, lane = o-pair ----
            {
                const float* H0 = g_Ht + (size_t)(2 * cb) * NE;
                const float* H1 = H0 + NE;
                int el = t >> 5;
                for (int ei = el; ei < ce; ei += 8) {
                    int p = pc0 + ei;
                    float h0 = H0[p], h1 = H1[p];
                    int nl = sl[ei];
                    float2 q0 = *(float2*)&Qs[nl * 130 + lane * 2];
                    float2 q1 = *(float2*)&Qs[nl * 130 + 64 + lane * 2];
                    float2 mv = *(float2*)&macc[ei * 64 + lane * 2];
                    mv.x += h0 * q0.x + h1 * q1.x;
                    mv.y += h0 * q0.y + h1 * q1.y;
                    *(float2*)&macc[ei * 64 + lane * 2] = mv;
                }
            }
            __syncthreads();
        }
        // ---- flush chunk: agg[dst] += macc + xb[src] ----
        {
            int el = t >> 5;
            for (int ei = el; ei < ce; ei += 8) {
                int p = pc0 + ei;
                int d = g_pdst[p];
                int s = sl[ei] + n0;
                int o = lane * 2;
                float2 mv = *(float2*)&macc[ei * 64 + o];
                float2 xv = *(const float2*)&g_xb[(size_t)s * 64 + o];
                atomicAdd(&g_agg[(size_t)d * 64 + o],     mv.x + xv.x);
                atomicAdd(&g_agg[(size_t)d * 64 + o + 1], mv.y + xv.y);
            }
        }
        __syncthreads();
    }
}

// ---------------- batch norm ----------------
__global__ void k_bn_zero() {
    int t = threadIdx.x;
    if (t < HID) { g_bnsum[t] = 0.f; g_bnsq[t] = 0.f; }
}
__global__ void k_bn_stats() {
    int t = threadIdx.x;
    int o = t & 63, s = t >> 6;
    float sum = 0.f, sq = 0.f;
    for (int n = blockIdx.x * 4 + s; n < NN; n += gridDim.x * 4) {
        float v = g_agg[(size_t)n * 64 + o];
        sum += v; sq += v * v;
    }
    __shared__ float ssum[256], ssq[256];
    ssum[t] = sum; ssq[t] = sq;
    __syncthreads();
    if (t < 128) { ssum[t] += ssum[t + 128]; ssq[t] += ssq[t + 128]; }
    __syncthreads();
    if (t < 64) {
        atomicAdd(&g_bnsum[t], ssum[t] + ssum[t + 64]);
        atomicAdd(&g_bnsq [t], ssq [t] + ssq [t + 64]);
    }
}
__global__ void k_bn_apply(const float* __restrict__ gamma,
                           const float* __restrict__ beta,
                           float* __restrict__ xout) {
    int i = blockIdx.x * blockDim.x + threadIdx.x;
    if (i >= NN * 64) return;
    int o = i & 63;
    float mu  = g_bnsum[o] * (1.f / NN);
    float var = g_bnsq[o] * (1.f / NN) - mu * mu;
    float v = gamma[o] * (g_agg[i] - mu) * rsqrtf(var + EPS_BN) + beta[o];
    xout[i] = fmaxf(v, 0.f);
}

// ---------------- pooling + final MLP ----------------
__global__ void k_pool_init() {
    int i = blockIdx.x * blockDim.x + threadIdx.x;
    if (i < NG * HID) g_pool[i] = 0.f;
}
__global__ void k_pool(const float* __restrict__ xl, const int* __restrict__ batch) {
    int i = blockIdx.x * blockDim.x + threadIdx.x;
    if (i >= NN * 64) return;
    int n = i >> 6, o = i & 63;
    int g = batch[n];
    atomicMax(reinterpret_cast<unsigned int*>(&g_pool[g * 64 + o]), __float_as_uint(xl[i]));
}
__global__ void k_final(const float* __restrict__ u,
                        const float* __restrict__ w1, const float* __restrict__ b1,
                        const float* __restrict__ w2, const float* __restrict__ b2,
                        float* __restrict__ out) {
    int g = blockIdx.x;
    int j = threadIdx.x;
    __shared__ float cat[72];
    __shared__ float red[64];
    if (j < 64) cat[j] = g_pool[g * 64 + j];
    if (j < 8)  cat[64 + j] = u[g * 8 + j];
    __syncthreads();
    float h = b1[j];
#pragma unroll
    for (int k = 0; k < 72; k++) h += cat[k] * w1[k * 64 + j];
    h = fmaxf(h, 0.f);
    red[j] = h * w2[j];
    __syncthreads();
    for (int s = 32; s > 0; s >>= 1) {
        if (j < s) red[j] += red[j + s];
        __syncthreads();
    }
    if (j == 0) out[g] = red[0] + b2[0];
}

// ---------------- host ----------------
extern "C" void kernel_launch(void* const* d_in, const int* in_sizes, int n_in,
                              void* d_out, int out_size) {
    const float* x       = (const float*)d_in[0];
    const int*   ei      = (const int*)  d_in[1];
    const float* ea      = (const float*)d_in[2];
    const int*   batch   = (const int*)  d_in[3];
    const float* u       = (const float*)d_in[4];
    const float* enn0_w1 = (const float*)d_in[5];
    const float* enn0_b1 = (const float*)d_in[6];
    const float* enn0_w2 = (const float*)d_in[7];
    const float* enn0_b2 = (const float*)d_in[8];
    const float* root0   = (const float*)d_in[9];
    const float* bias0   = (const float*)d_in[10];
    const float* gamma0  = (const float*)d_in[11];
    const float* beta0   = (const float*)d_in[12];
    const float* enn_w1  = (const float*)d_in[13];
    const float* enn_b1  = (const float*)d_in[14];
    const float* enn_w2  = (const float*)d_in[15];
    const float* enn_b2  = (const float*)d_in[16];
    const float* root_l  = (const float*)d_in[17];
    const float* bias_l  = (const float*)d_in[18];
    const float* gamma_l = (const float*)d_in[19];
    const float* beta_l  = (const float*)d_in[20];
    const float* pp_w1   = (const float*)d_in[21];
    const float* pp_b1   = (const float*)d_in[22];
    const float* pp_w2   = (const float*)d_in[23];
    const float* pp_b2   = (const float*)d_in[24];

    const int* src  = ei;
    const int* dste = ei + NE;

    cudaFuncSetAttribute(k_fused, cudaFuncAttributeMaxDynamicSharedMemorySize, FS_TOTAL);

    void* pA; cudaGetSymbolAddress(&pA, g_xA);
    void* pB; cudaGetSymbolAddress(&pB, g_xB);
    float* xA = (float*)pA;
    float* xB = (float*)pB;

    k_zero_cnt<<<(NN + 255) / 256, 256>>>();
    k_count  <<<(NE + 255) / 256, 256>>>(src);
    k_scan   <<<1, 1024>>>();
    k_scatter<<<(NE + 255) / 256, 256>>>(src, dste);

    const float* xin = x;
    int C = IN_CH;
    float* xout = xA;

    for (int l = 0; l < 4; l++) {
        const float *w1, *b1, *w2, *b2, *rt, *bs, *gm, *bt;
        if (l == 0) {
            w1 = enn0_w1; b1 = enn0_b1; w2 = enn0_w2; b2 = enn0_b2;
            rt = root0; bs = bias0; gm = gamma0; bt = beta0;
        } else {
            int m = l - 1;
            w1 = enn_w1 + (size_t)m * EIN * 128;
            b1 = enn_b1 + (size_t)m * 128;
            w2 = enn_w2 + (size_t)m * 128 * 4096;
            b2 = enn_b2 + (size_t)m * 4096;
            rt = root_l + (size_t)m * 64 * 64;
            bs = bias_l + (size_t)m * 64;
            gm = gamma_l + (size_t)m * 64;
            bt = beta_l + (size_t)m * 64;
        }
        k_wsplit  <<<(8192 * 192 + 255) / 256, 256>>>(w2, C);
        k_edge_h  <<<(NE + EPB - 1) / EPB, 128>>>(ea, w1, b1);
        k_node_pre<<<(NN + 3) / 4, 256>>>(xin, C, rt, bs, b2);
        k_fused   <<<(NN + NODE_G - 1) / NODE_G, 256, FS_TOTAL>>>(xin, C);
        k_bn_zero <<<1, 64>>>();
        k_bn_stats<<<128, 256>>>();
        k_bn_apply<<<(NN * 64 + 255) / 256, 256>>>(gm, bt, xout);

        xin = xout;
        C = HID;
        xout = (xout == xA) ? xB : xA;
    }

    k_pool_init<<<(NG * HID + 255) / 256, 256>>>();
    k_pool     <<<(NN * 64 + 255) / 256, 256>>>(xin, batch);
    k_final    <<<NG, 64>>>(u, pp_w1, pp_b1, pp_w2, pp_b2, (float*)d_out);
}

// round 7
// speedup vs baseline: 1.3029x; 1.3029x over previous
#include <cuda_runtime.h>
#include <cuda_bf16.h>
#include <math.h>

typedef unsigned int u32;
typedef unsigned long long u64;

#define NN 10000
#define NE 50000
#define IN_CH 32
#define EIN 16
#define GIN 8
#define HID 64
#define NG 64
#define QW 8192
#define EPS_BN 1e-5f

// ---------------- device scratch ----------------
__device__ __align__(16) __nv_bfloat16 g_Wbf[8192 * 192]; // [j=c*64+o][3K pack hi|lo|hi], row stride 192
__device__ float g_H [(size_t)NE * 128];   // perm-ordered: [p][c]
__device__ float g_Q [(size_t)NN * QW];
__device__ float g_xA[NN * HID];
__device__ float g_xB[NN * HID];
__device__ float g_agg[NN * HID];
__device__ float g_xb [NN * HID];
__device__ int   g_cnt[NN];
__device__ int   g_off[NN + 1];
__device__ int   g_cur[NN];
__device__ int   g_perm[NE];
__device__ int   g_pdst[NE];
__device__ float g_bnsum[HID];
__device__ float g_bnsq [HID];
__device__ float g_pool[NG * HID];

// ---------------- PTX helpers (sm_80+ baseline) ----------------
__device__ __forceinline__ u32 smem_u32(const void* p) {
    u32 a;
    asm("{ .reg .u64 t; cvta.to.shared.u64 t, %1; cvt.u32.u64 %0, t; }" : "=r"(a) : "l"(p));
    return a;
}
__device__ __forceinline__ void ldsm_x4(u32& r0, u32& r1, u32& r2, u32& r3, u32 addr) {
    asm volatile("ldmatrix.sync.aligned.m8n8.x4.shared.b16 {%0,%1,%2,%3}, [%4];"
                 : "=r"(r0), "=r"(r1), "=r"(r2), "=r"(r3) : "r"(addr));
}
__device__ __forceinline__ void ldsm_x2(u32& r0, u32& r1, u32 addr) {
    asm volatile("ldmatrix.sync.aligned.m8n8.x2.shared.b16 {%0,%1}, [%2];"
                 : "=r"(r0), "=r"(r1) : "r"(addr));
}
__device__ __forceinline__ void mma16816(float* c, const u32* a, const u32* b) {
    asm volatile(
        "mma.sync.aligned.m16n8k16.row.col.f32.bf16.bf16.f32 "
        "{%0,%1,%2,%3}, {%4,%5,%6,%7}, {%8,%9}, {%0,%1,%2,%3};"
        : "+f"(c[0]), "+f"(c[1]), "+f"(c[2]), "+f"(c[3])
        : "r"(a[0]), "r"(a[1]), "r"(a[2]), "r"(a[3]), "r"(b[0]), "r"(b[1]));
}

// ---------------- CSR build ----------------
__global__ void k_zero_cnt() {
    int i = blockIdx.x * blockDim.x + threadIdx.x;
    if (i < NN) g_cnt[i] = 0;
}
__global__ void k_count(const int* __restrict__ src) {
    int e = blockIdx.x * blockDim.x + threadIdx.x;
    if (e < NE) atomicAdd(&g_cnt[src[e]], 1);
}
__global__ void k_scan() {
    __shared__ int part[1024];
    int t = threadIdx.x;
    const int CH = (NN + 1023) / 1024;
    int base = t * CH;
    int s = 0;
    for (int i = 0; i < CH; i++) {
        int idx = base + i;
        if (idx < NN) s += g_cnt[idx];
    }
    part[t] = s;
    __syncthreads();
    for (int d = 1; d < 1024; d <<= 1) {
        int v = (t >= d) ? part[t - d] : 0;
        __syncthreads();
        part[t] += v;
        __syncthreads();
    }
    int pre = (t == 0) ? 0 : part[t - 1];
    for (int i = 0; i < CH; i++) {
        int idx = base + i;
        if (idx < NN) {
            g_off[idx] = pre;
            g_cur[idx] = pre;
            pre += g_cnt[idx];
        }
    }
    if (t == 1023) g_off[NN] = part[1023];
}
__global__ void k_scatter(const int* __restrict__ src, const int* __restrict__ dst) {
    int e = blockIdx.x * blockDim.x + threadIdx.x;
    if (e < NE) {
        int p = atomicAdd(&g_cur[src[e]], 1);
        g_perm[p] = e;
        g_pdst[p] = dst[e];
    }
}

// ---------------- W2 split, coalesced via SMEM transpose ----------------
// CTA per c (grid 128). Packs blocks [Whi | Wlo | Whi], widths K each, into first 3K cols.
__global__ void k_wsplit2(const float* __restrict__ w2, int K) {
    __shared__ float ws[64 * 65];
    int c = blockIdx.x;
    int t = threadIdx.x;  // 256
    for (int idx = t; idx < K * 64; idx += 256) {
        int k = idx >> 6, o = idx & 63;
        ws[k * 65 + o] = w2[(size_t)c * (K * 64) + idx];
    }
    __syncthreads();
    int wid = t >> 5, lane = t & 31;
    int np = (3 * K) >> 1;   // u32 pairs per row
    u32* Wr = (u32*)g_Wbf;
    for (int o = wid; o < 64; o += 8) {
        size_t j = (size_t)(c * 64 + o);
        for (int pc = lane; pc < np; pc += 32) {
            int j2 = pc * 2;
            int b = j2 / K, kk = j2 - b * K;
            float v0 = ws[kk * 65 + o];
            float v1 = ws[(kk + 1) * 65 + o];
            __nv_bfloat16 h0 = __float2bfloat16(v0);
            __nv_bfloat16 h1 = __float2bfloat16(v1);
            u32 pk;
            if (b == 1) {
                __nv_bfloat16 l0 = __float2bfloat16(v0 - __bfloat162float(h0));
                __nv_bfloat16 l1 = __float2bfloat16(v1 - __bfloat162float(h1));
                pk = (u32)__bfloat16_as_ushort(l0) | ((u32)__bfloat16_as_ushort(l1) << 16);
            } else {
                pk = (u32)__bfloat16_as_ushort(h0) | ((u32)__bfloat16_as_ushort(h1) << 16);
            }
            Wr[j * 96 + pc] = pk;
        }
    }
}

// ---------------- edge hidden, perm-ordered rows: g_H[p][c] ----------------
#define EPC 25
__global__ void k_edge_h(const float* __restrict__ ea,
                         const float* __restrict__ w1,
                         const float* __restrict__ b1) {
    __shared__ float ws[EIN * 128];
    __shared__ float bs[128];
    __shared__ float eas[EIN];
    int c = threadIdx.x;  // 128
    for (int i = 0; i < EIN; i++) ws[i * 128 + c] = w1[i * 128 + c];
    bs[c] = b1[c];
    int p0 = blockIdx.x * EPC;
    int p1 = min(p0 + EPC, NE);
    for (int p = p0; p < p1; p++) {
        __syncthreads();
        if (c < EIN) eas[c] = ea[(size_t)g_perm[p] * EIN + c];
        __syncthreads();
        float s = bs[c];
#pragma unroll
        for (int i = 0; i < EIN; i++) s += eas[i] * ws[i * 128 + c];
        g_H[(size_t)p * 128 + c] = fmaxf(s, 0.f);
    }
}

// ---------------- node pre: agg = x@root + bias ; xb = x@b2resh ----------------
__global__ void k_node_pre(const float* __restrict__ x, int C,
                           const float* __restrict__ root,
                           const float* __restrict__ bias,
                           const float* __restrict__ b2) {
    __shared__ float xs[4][64];
    __shared__ float rs[64 * 64];
    __shared__ float b2s[64 * 64];
    int t = threadIdx.x;
    int o = t & 63, s = t >> 6;
    for (int i = t; i < C * 64; i += 256) { rs[i] = root[i]; b2s[i] = b2[i]; }
    int n = blockIdx.x * 4 + s;
    if (n < NN) {
        for (int k = o; k < C; k += 64) xs[s][k] = x[(size_t)n * C + k];
    }
    __syncthreads();
    if (n < NN) {
        float a = bias[o], xbv = 0.f;
        for (int k = 0; k < C; k++) {
            float xv = xs[s][k];
            a   += xv * rs [k * 64 + o];
            xbv += xv * b2s[k * 64 + o];
        }
        g_agg[n * 64 + o] = a;
        g_xb [n * 64 + o] = xbv;
    }
}

// ---------------- mma.sync Q GEMM: 128x128 tile, K'=3K hi/lo split ----------------
#define ASTRIDE 200

__global__ void __launch_bounds__(256, 1) k_qgemm_mma(const float* __restrict__ X, int K) {
    extern __shared__ __nv_bfloat16 smem[];
    __nv_bfloat16* As = smem;
    __nv_bfloat16* Bs = smem + 128 * ASTRIDE;
    int t = threadIdx.x, wid = t >> 5, lane = t & 31;
    int row0 = blockIdx.y * 128, col0 = blockIdx.x * 128;
    int nk16 = (3 * K) >> 4;   // 6 or 12 ksteps

    // ---- A fill: row r = t/2, k-half (t&1); blocks [hi|hi|lo] at offsets 0,K,2K ----
    {
        int r = t >> 1;
        int n = row0 + r;
        int kbeg = (t & 1) * (K >> 1);
        int kend = kbeg + (K >> 1);
        u32* Arow = (u32*)(As + r * ASTRIDE);
        for (int k = kbeg; k < kend; k += 2) {
            float v0 = 0.f, v1 = 0.f;
            if (n < NN) {
                v0 = X[(size_t)n * K + k];
                v1 = X[(size_t)n * K + k + 1];
            }
            __nv_bfloat16 h0 = __float2bfloat16(v0);
            __nv_bfloat16 h1 = __float2bfloat16(v1);
            __nv_bfloat16 l0 = __float2bfloat16(v0 - __bfloat162float(h0));
            __nv_bfloat16 l1 = __float2bfloat16(v1 - __bfloat162float(h1));
            u32 hp = (u32)__bfloat16_as_ushort(h0) | ((u32)__bfloat16_as_ushort(h1) << 16);
            u32 lp = (u32)__bfloat16_as_ushort(l0) | ((u32)__bfloat16_as_ushort(l1) << 16);
            Arow[k >> 1]           = hp;
            Arow[(K + k) >> 1]     = hp;
            Arow[(2 * K + k) >> 1] = lp;
        }
    }
    // ---- B fill: 128 rows x 3K/8 uint4 from g_Wbf (row stride 96 u32) ----
    {
        const uint4* W4 = (const uint4*)g_Wbf;
        uint4* B4 = (uint4*)Bs;
        int nq = (3 * K) >> 3;   // uint4 per row (24 or 12)
        int tot = 128 * nq;
        for (int i = t; i < tot; i += 256) {
            int r = i / nq, q = i - r * nq;
            B4[r * 25 + q] = W4[(size_t)(col0 + r) * 24 + q];
        }
    }
    __syncthreads();

    int wm = (wid & 3) * 32;
    int wn = (wid >> 2) * 64;
    u32 a_base = smem_u32(As);
    u32 b_base = smem_u32(Bs);

    float acc[2][8][4];
#pragma unroll
    for (int i = 0; i < 2; i++)
#pragma unroll
        for (int j = 0; j < 8; j++)
#pragma unroll
            for (int q = 0; q < 4; q++) acc[i][j][q] = 0.f;

#pragma unroll 6
    for (int ks = 0; ks < nk16; ks++) {
        int k0 = ks * 16;
        u32 a[2][4];
#pragma unroll
        for (int i = 0; i < 2; i++) {
            u32 addr = a_base + (u32)(((wm + i * 16 + (lane & 15)) * ASTRIDE +
                                        k0 + ((lane >> 4) << 3)) * 2);
            ldsm_x4(a[i][0], a[i][1], a[i][2], a[i][3], addr);
        }
        u32 b[8][2];
#pragma unroll
        for (int j = 0; j < 8; j++) {
            u32 addr = b_base + (u32)(((wn + j * 8 + (lane & 7)) * ASTRIDE +
                                        k0 + ((lane >> 3) & 1) * 8) * 2);
            ldsm_x2(b[j][0], b[j][1], addr);
        }
#pragma unroll
        for (int i = 0; i < 2; i++)
#pragma unroll
            for (int j = 0; j < 8; j++)
                mma16816(acc[i][j], a[i], b[j]);
    }

#pragma unroll
    for (int i = 0; i < 2; i++) {
        int m0 = row0 + wm + i * 16 + (lane >> 2);
#pragma unroll
        for (int j = 0; j < 8; j++) {
            int col = col0 + wn + j * 8 + (lane & 3) * 2;
            if (m0 < NN) {
                float2* p = (float2*)&g_Q[(size_t)m0 * QW + col];
                *p = make_float2(acc[i][j][0], acc[i][j][1]);
            }
            if (m0 + 8 < NN) {
                float2* p = (float2*)&g_Q[(size_t)(m0 + 8) * QW + col];
                *p = make_float2(acc[i][j][2], acc[i][j][3]);
            }
        }
    }
}

// ---------------- edge messages: 256 thr, 4 edge slots per barrier ----------------
__global__ void k_edge_msg() {
    int n = blockIdx.x;
    int e0 = g_off[n], e1 = g_off[n + 1];
    if (e0 >= e1) return;
    int t = threadIdx.x;           // 256
    int o = t & 63, slot = t >> 6; // 4 slots
    __shared__ float Qs[QW];
    __shared__ float hs[4][128];
    __shared__ float xbs[64];
    for (int i = t; i < QW; i += 256) Qs[i] = g_Q[(size_t)n * QW + i];
    if (t < 64) xbs[t] = g_xb[n * 64 + t];
    for (int ei = e0; ei < e1; ei += 4) {
        int p = ei + slot;
        bool valid = (p < e1);
        __syncthreads();
        if (valid) {
            hs[slot][o]      = g_H[(size_t)p * 128 + o];
            hs[slot][64 + o] = g_H[(size_t)p * 128 + 64 + o];
        }
        __syncthreads();
        if (valid) {
            float m = xbs[o];
#pragma unroll
            for (int c = 0; c < 128; c++) m += hs[slot][c] * Qs[c * 64 + o];
            atomicAdd(&g_agg[(size_t)g_pdst[p] * 64 + o], m);
        }
    }
}

// ---------------- batch norm ----------------
__global__ void k_bn_zero() {
    int t = threadIdx.x;
    if (t < HID) { g_bnsum[t] = 0.f; g_bnsq[t] = 0.f; }
}
__global__ void k_bn_stats() {
    int t = threadIdx.x;
    int o = t & 63, s = t >> 6;
    float sum = 0.f, sq = 0.f;
    for (int n = blockIdx.x * 4 + s; n < NN; n += gridDim.x * 4) {
        float v = g_agg[(size_t)n * 64 + o];
        sum += v; sq += v * v;
    }
    __shared__ float ssum[256], ssq[256];
    ssum[t] = sum; ssq[t] = sq;
    __syncthreads();
    if (t < 128) { ssum[t] += ssum[t + 128]; ssq[t] += ssq[t + 128]; }
    __syncthreads();
    if (t < 64) {
        atomicAdd(&g_bnsum[t], ssum[t] + ssum[t + 64]);
        atomicAdd(&g_bnsq [t], ssq [t] + ssq [t + 64]);
    }
}
__global__ void k_bn_apply(const float* __restrict__ gamma,
                           const float* __restrict__ beta,
                           float* __restrict__ xout) {
    int i = blockIdx.x * blockDim.x + threadIdx.x;
    if (i >= NN * 64) return;
    int o = i & 63;
    float mu  = g_bnsum[o] * (1.f / NN);
    float var = g_bnsq[o] * (1.f / NN) - mu * mu;
    float v = gamma[o] * (g_agg[i] - mu) * rsqrtf(var + EPS_BN) + beta[o];
    xout[i] = fmaxf(v, 0.f);
}

// ---------------- pooling + final MLP ----------------
__global__ void k_pool_init() {
    int i = blockIdx.x * blockDim.x + threadIdx.x;
    if (i < NG * HID) g_pool[i] = 0.f;
}
__global__ void k_pool(const float* __restrict__ xl, const int* __restrict__ batch) {
    int i = blockIdx.x * blockDim.x + threadIdx.x;
    if (i >= NN * 64) return;
    int n = i >> 6, o = i & 63;
    int g = batch[n];
    atomicMax(reinterpret_cast<unsigned int*>(&g_pool[g * 64 + o]), __float_as_uint(xl[i]));
}
__global__ void k_final(const float* __restrict__ u,
                        const float* __restrict__ w1, const float* __restrict__ b1,
                        const float* __restrict__ w2, const float* __restrict__ b2,
                        float* __restrict__ out) {
    int g = blockIdx.x;
    int j = threadIdx.x;
    __shared__ float cat[72];
    __shared__ float red[64];
    if (j < 64) cat[j] = g_pool[g * 64 + j];
    if (j < 8)  cat[64 + j] = u[g * 8 + j];
    __syncthreads();
    float h = b1[j];
#pragma unroll
    for (int k = 0; k < 72; k++) h += cat[k] * w1[k * 64 + j];
    h = fmaxf(h, 0.f);
    red[j] = h * w2[j];
    __syncthreads();
    for (int s = 32; s > 0; s >>= 1) {
        if (j < s) red[j] += red[j + s];
        __syncthreads();
    }
    if (j == 0) out[g] = red[0] + b2[0];
}

// ---------------- host ----------------
extern "C" void kernel_launch(void* const* d_in, const int* in_sizes, int n_in,
                              void* d_out, int out_size) {
    const float* x       = (const float*)d_in[0];
    const int*   ei      = (const int*)  d_in[1];
    const float* ea      = (const float*)d_in[2];
    const int*   batch   = (const int*)  d_in[3];
    const float* u       = (const float*)d_in[4];
    const float* enn0_w1 = (const float*)d_in[5];
    const float* enn0_b1 = (const float*)d_in[6];
    const float* enn0_w2 = (const float*)d_in[7];
    const float* enn0_b2 = (const float*)d_in[8];
    const float* root0   = (const float*)d_in[9];
    const float* bias0   = (const float*)d_in[10];
    const float* gamma0  = (const float*)d_in[11];
    const float* beta0   = (const float*)d_in[12];
    const float* enn_w1  = (const float*)d_in[13];
    const float* enn_b1  = (const float*)d_in[14];
    const float* enn_w2  = (const float*)d_in[15];
    const float* enn_b2  = (const float*)d_in[16];
    const float* root_l  = (const float*)d_in[17];
    const float* bias_l  = (const float*)d_in[18];
    const float* gamma_l = (const float*)d_in[19];
    const float* beta_l  = (const float*)d_in[20];
    const float* pp_w1   = (const float*)d_in[21];
    const float* pp_b1   = (const float*)d_in[22];
    const float* pp_w2   = (const float*)d_in[23];
    const float* pp_b2   = (const float*)d_in[24];

    const int* src  = ei;
    const int* dste = ei + NE;

    const int QG_SMEM = 2 * 128 * ASTRIDE * 2;  // 102400 B
    cudaFuncSetAttribute(k_qgemm_mma, cudaFuncAttributeMaxDynamicSharedMemorySize, QG_SMEM);

    void* pA; cudaGetSymbolAddress(&pA, g_xA);
    void* pB; cudaGetSymbolAddress(&pB, g_xB);
    float* xA = (float*)pA;
    float* xB = (float*)pB;

    k_zero_cnt<<<(NN + 255) / 256, 256>>>();
    k_count  <<<(NE + 255) / 256, 256>>>(src);
    k_scan   <<<1, 1024>>>();
    k_scatter<<<(NE + 255) / 256, 256>>>(src, dste);

    const float* xin = x;
    int C = IN_CH;
    float* xout = xA;

    for (int l = 0; l < 4; l++) {
        const float *w1, *b1, *w2, *b2, *rt, *bs, *gm, *bt;
        if (l == 0) {
            w1 = enn0_w1; b1 = enn0_b1; w2 = enn0_w2; b2 = enn0_b2;
            rt = root0; bs = bias0; gm = gamma0; bt = beta0;
        } else {
            int m = l - 1;
            w1 = enn_w1 + (size_t)m * EIN * 128;
            b1 = enn_b1 + (size_t)m * 128;
            w2 = enn_w2 + (size_t)m * 128 * 4096;
            b2 = enn_b2 + (size_t)m * 4096;
            rt = root_l + (size_t)m * 64 * 64;
            bs = bias_l + (size_t)m * 64;
            gm = gamma_l + (size_t)m * 64;
            bt = beta_l + (size_t)m * 64;
        }
        k_wsplit2 <<<128, 256>>>(w2, C);
        k_edge_h  <<<(NE + EPC - 1) / EPC, 128>>>(ea, w1, b1);
        k_node_pre<<<(NN + 3) / 4, 256>>>(xin, C, rt, bs, b2);
        dim3 gq(QW / 128, (NN + 127) / 128);
        k_qgemm_mma<<<gq, 256, QG_SMEM>>>(xin, C);
        k_edge_msg<<<NN, 256>>>();
        k_bn_zero <<<1, 64>>>();
        k_bn_stats<<<128, 256>>>();
        k_bn_apply<<<(NN * 64 + 255) / 256, 256>>>(gm, bt, xout);

        xin = xout;
        C = HID;
        xout = (xout == xA) ? xB : xA;
    }

    k_pool_init<<<(NG * HID + 255) / 256, 256>>>();
    k_pool     <<<(NN * 64 + 255) / 256, 256>>>(xin, batch);
    k_final    <<<NG, 64>>>(u, pp_w1, pp_b1, pp_w2, pp_b2, (float*)d_out);
}

// round 8
// speedup vs baseline: 1.4649x; 1.1243x over previous
#include <cuda_runtime.h>
#include <cuda_bf16.h>
#include <math.h>

typedef unsigned int u32;
typedef unsigned long long u64;

#define NN 10000
#define NE 50000
#define IN_CH 32
#define EIN 16
#define GIN 8
#define HID 64
#define NG 64
#define EPS_BN 1e-5f

#define NODE_G 68     // nodes per fused CTA -> 148 CTAs = one wave
#define MPAD 96       // mma M pad (6 x 16)
#define ECAP 384      // SMEM edge accumulator capacity
#define ASTRIDE 200   // bf16 elems per A/B SMEM row (400B)
#define QSTRIDE 136   // f32 elems per Qs row (bank-conflict-free)

// ---------------- device scratch ----------------
__device__ __align__(16) __nv_bfloat16 g_Wbf[8192 * 192]; // [j=c*64+o][3K pack hi|lo|hi], row stride 192
__device__ float g_H [(size_t)NE * 128];   // perm-ordered: [p][c]
__device__ float g_xA[NN * HID];
__device__ float g_xB[NN * HID];
__device__ float g_agg[NN * HID];
__device__ float g_xb [NN * HID];
__device__ int   g_cnt[NN];
__device__ int   g_off[NN + 1];
__device__ int   g_cur[NN];
__device__ int   g_perm[NE];
__device__ int   g_psrc[NE];
__device__ int   g_pdst[NE];
__device__ float g_bnsum[HID];
__device__ float g_bnsq [HID];
__device__ float g_pool[NG * HID];

// ---------------- PTX helpers (sm_80+ baseline) ----------------
__device__ __forceinline__ u32 smem_u32(const void* p) {
    u32 a;
    asm("{ .reg .u64 t; cvta.to.shared.u64 t, %1; cvt.u32.u64 %0, t; }" : "=r"(a) : "l"(p));
    return a;
}
__device__ __forceinline__ void ldsm_x4(u32& r0, u32& r1, u32& r2, u32& r3, u32 addr) {
    asm volatile("ldmatrix.sync.aligned.m8n8.x4.shared.b16 {%0,%1,%2,%3}, [%4];"
                 : "=r"(r0), "=r"(r1), "=r"(r2), "=r"(r3) : "r"(addr));
}
__device__ __forceinline__ void ldsm_x2(u32& r0, u32& r1, u32 addr) {
    asm volatile("ldmatrix.sync.aligned.m8n8.x2.shared.b16 {%0,%1}, [%2];"
                 : "=r"(r0), "=r"(r1) : "r"(addr));
}
__device__ __forceinline__ void mma16816(float* c, const u32* a, const u32* b) {
    asm volatile(
        "mma.sync.aligned.m16n8k16.row.col.f32.bf16.bf16.f32 "
        "{%0,%1,%2,%3}, {%4,%5,%6,%7}, {%8,%9}, {%0,%1,%2,%3};"
        : "+f"(c[0]), "+f"(c[1]), "+f"(c[2]), "+f"(c[3])
        : "r"(a[0]), "r"(a[1]), "r"(a[2]), "r"(a[3]), "r"(b[0]), "r"(b[1]));
}
__device__ __forceinline__ void cpasync16(u32 saddr, const void* gaddr) {
    asm volatile("cp.async.ca.shared.global [%0], [%1], 16;" :: "r"(saddr), "l"(gaddr) : "memory");
}
__device__ __forceinline__ void cp_commit() {
    asm volatile("cp.async.commit_group;" ::: "memory");
}
__device__ __forceinline__ void cp_wait0() {
    asm volatile("cp.async.wait_group 0;" ::: "memory");
}

// ---------------- CSR build ----------------
__global__ void k_zero_cnt() {
    int i = blockIdx.x * blockDim.x + threadIdx.x;
    if (i < NN) g_cnt[i] = 0;
}
__global__ void k_count(const int* __restrict__ src) {
    int e = blockIdx.x * blockDim.x + threadIdx.x;
    if (e < NE) atomicAdd(&g_cnt[src[e]], 1);
}
__global__ void k_scan() {
    __shared__ int part[1024];
    int t = threadIdx.x;
    const int CH = (NN + 1023) / 1024;
    int base = t * CH;
    int s = 0;
    for (int i = 0; i < CH; i++) {
        int idx = base + i;
        if (idx < NN) s += g_cnt[idx];
    }
    part[t] = s;
    __syncthreads();
    for (int d = 1; d < 1024; d <<= 1) {
        int v = (t >= d) ? part[t - d] : 0;
        __syncthreads();
        part[t] += v;
        __syncthreads();
    }
    int pre = (t == 0) ? 0 : part[t - 1];
    for (int i = 0; i < CH; i++) {
        int idx = base + i;
        if (idx < NN) {
            g_off[idx] = pre;
            g_cur[idx] = pre;
            pre += g_cnt[idx];
        }
    }
    if (t == 1023) g_off[NN] = part[1023];
}
__global__ void k_scatter(const int* __restrict__ src, const int* __restrict__ dst) {
    int e = blockIdx.x * blockDim.x + threadIdx.x;
    if (e < NE) {
        int s = src[e];
        int p = atomicAdd(&g_cur[s], 1);
        g_perm[p] = e;
        g_psrc[p] = s;
        g_pdst[p] = dst[e];
    }
}

// ---------------- W2 split, coalesced via SMEM transpose ----------------
__global__ void k_wsplit2(const float* __restrict__ w2, int K) {
    __shared__ float ws[64 * 65];
    int c = blockIdx.x;
    int t = threadIdx.x;  // 256
    for (int idx = t; idx < K * 64; idx += 256) {
        int k = idx >> 6, o = idx & 63;
        ws[k * 65 + o] = w2[(size_t)c * (K * 64) + idx];
    }
    __syncthreads();
    int wid = t >> 5, lane = t & 31;
    int np = (3 * K) >> 1;
    u32* Wr = (u32*)g_Wbf;
    for (int o = wid; o < 64; o += 8) {
        size_t j = (size_t)(c * 64 + o);
        for (int pc = lane; pc < np; pc += 32) {
            int j2 = pc * 2;
            int b = j2 / K, kk = j2 - b * K;
            float v0 = ws[kk * 65 + o];
            float v1 = ws[(kk + 1) * 65 + o];
            __nv_bfloat16 h0 = __float2bfloat16(v0);
            __nv_bfloat16 h1 = __float2bfloat16(v1);
            u32 pk;
            if (b == 1) {
                __nv_bfloat16 l0 = __float2bfloat16(v0 - __bfloat162float(h0));
                __nv_bfloat16 l1 = __float2bfloat16(v1 - __bfloat162float(h1));
                pk = (u32)__bfloat16_as_ushort(l0) | ((u32)__bfloat16_as_ushort(l1) << 16);
            } else {
                pk = (u32)__bfloat16_as_ushort(h0) | ((u32)__bfloat16_as_ushort(h1) << 16);
            }
            Wr[j * 96 + pc] = pk;
        }
    }
}

// ---------------- edge hidden, perm-ordered rows: g_H[p][c] ----------------
#define EPC 25
__global__ void k_edge_h(const float* __restrict__ ea,
                         const float* __restrict__ w1,
                         const float* __restrict__ b1) {
    __shared__ float ws[EIN * 128];
    __shared__ float bs[128];
    __shared__ float eas[EIN];
    int c = threadIdx.x;  // 128
    for (int i = 0; i < EIN; i++) ws[i * 128 + c] = w1[i * 128 + c];
    bs[c] = b1[c];
    int p0 = blockIdx.x * EPC;
    int p1 = min(p0 + EPC, NE);
    for (int p = p0; p < p1; p++) {
        __syncthreads();
        if (c < EIN) eas[c] = ea[(size_t)g_perm[p] * EIN + c];
        __syncthreads();
        float s = bs[c];
#pragma unroll
        for (int i = 0; i < EIN; i++) s += eas[i] * ws[i * 128 + c];
        g_H[(size_t)p * 128 + c] = fmaxf(s, 0.f);
    }
}

// ---------------- node pre: agg = x@root + bias ; xb = x@b2resh ----------------
__global__ void k_node_pre(const float* __restrict__ x, int C,
                           const float* __restrict__ root,
                           const float* __restrict__ bias,
                           const float* __restrict__ b2) {
    __shared__ float xs[4][64];
    __shared__ float rs[64 * 64];
    __shared__ float b2s[64 * 64];
    int t = threadIdx.x;
    int o = t & 63, s = t >> 6;
    for (int i = t; i < C * 64; i += 256) { rs[i] = root[i]; b2s[i] = b2[i]; }
    int n = blockIdx.x * 4 + s;
    if (n < NN) {
        for (int k = o; k < C; k += 64) xs[s][k] = x[(size_t)n * C + k];
    }
    __syncthreads();
    if (n < NN) {
        float a = bias[o], xbv = 0.f;
        for (int k = 0; k < C; k++) {
            float xv = xs[s][k];
            a   += xv * rs [k * 64 + o];
            xbv += xv * b2s[k * 64 + o];
        }
        g_agg[n * 64 + o] = a;
        g_xb [n * 64 + o] = xbv;
    }
}

// ---------------- FUSED v2: Q tiles (mma) + edge messages, no Q in DRAM ----------------
// SMEM (bytes): As 96x200 bf16 = 38400 | Bs 128x200 bf16 = 51200 |
//               Qs 68x136 f32 = 36992  | macc 384x64 f32 = 98304 | sl 384 i32 = 1536
#define FO_B  38400
#define FO_Q  89600
#define FO_M  126592
#define FO_SL 224896
#define FO_TOTAL 226432

__global__ void __launch_bounds__(512, 1) k_fused(const float* __restrict__ X, int K) {
    extern __shared__ char smem[];
    __nv_bfloat16* As = (__nv_bfloat16*)smem;
    __nv_bfloat16* Bs = (__nv_bfloat16*)(smem + FO_B);
    float* Qs   = (float*)(smem + FO_Q);
    float* macc = (float*)(smem + FO_M);
    int*   sl   = (int*)(smem + FO_SL);

    int t = threadIdx.x, w = t >> 5, lane = t & 31;
    int n0 = blockIdx.x * NODE_G;
    int nend = min(n0 + NODE_G, NN);
    int p0 = g_off[n0];
    int p1 = g_off[nend];
    int ce = p1 - p0;
    if (ce <= 0) return;
    int ceM = min(ce, ECAP);
    int nk16 = (3 * K) >> 4;        // 6 (K=32) or 12 (K=64)
    int nq   = nk16 * 2;            // uint4 per B row

    u32 a_base = smem_u32(As);
    u32 b_base = smem_u32(Bs);

    // ---- prefetch B(0) ----
    {
        const char* Wsrc = (const char*)g_Wbf;
        for (int i = t; i < 128 * nq; i += 512) {
            int r = i / nq, q = i - r * nq;
            cpasync16(b_base + (u32)(r * 400 + q * 16),
                      Wsrc + (size_t)r * 384 + q * 16);
        }
        cp_commit();
    }

    // ---- A' fill: [hi | hi | lo] at word offsets 0, K/2, K ----
    {
        int half = K >> 1;
        u32* Au = (u32*)As;
        for (int idx = t; idx < MPAD * half; idx += 512) {
            int r = idx / half, kp = idx - r * half;
            int k = kp * 2;
            int n = n0 + r;
            float v0 = 0.f, v1 = 0.f;
            if (r < NODE_G && n < NN) {
                v0 = X[(size_t)n * K + k];
                v1 = X[(size_t)n * K + k + 1];
            }
            __nv_bfloat16 h0 = __float2bfloat16(v0);
            __nv_bfloat16 h1 = __float2bfloat16(v1);
            __nv_bfloat16 l0 = __float2bfloat16(v0 - __bfloat162float(h0));
            __nv_bfloat16 l1 = __float2bfloat16(v1 - __bfloat162float(h1));
            u32 hp = (u32)__bfloat16_as_ushort(h0) | ((u32)__bfloat16_as_ushort(h1) << 16);
            u32 lp = (u32)__bfloat16_as_ushort(l0) | ((u32)__bfloat16_as_ushort(l1) << 16);
            u32* Arow = Au + r * 100;
            Arow[kp]            = hp;
            Arow[half + kp]     = hp;
            Arow[2 * half + kp] = lp;
        }
    }
    // ---- edge meta + macc zero ----
    for (int i = t; i < ceM; i += 512) sl[i] = g_psrc[p0 + i] - n0;
    {
        float4* m4 = (float4*)macc;
        for (int i = t; i < ECAP * 16; i += 512) m4[i] = make_float4(0.f, 0.f, 0.f, 0.f);
    }

    // warp mma tile: wm = (w&1)*48 (3 m16), wn = (w>>1)*16 (2 n8)
    int wm = (w & 1) * 48;
    int wn = (w >> 1) * 16;
    int eh = lane >> 4;         // edge half (0/1)
    int ol = lane & 15;         // o-quad index
    int npair = (ceM + 1) >> 1;

    for (int cb = 0; cb < 64; cb++) {
        cp_wait0();
        __syncthreads();   // B(cb) ready; edge(cb-1) done; sl/macc ready (cb=0)

        // ---- mma: 96x128 = warp 48x16, acc 6 frags ----
        float acc[3][2][4];
#pragma unroll
        for (int mi = 0; mi < 3; mi++)
#pragma unroll
            for (int j = 0; j < 2; j++)
#pragma unroll
                for (int q = 0; q < 4; q++) acc[mi][j][q] = 0.f;

        for (int ks = 0; ks < nk16; ks++) {
            int k0 = ks * 16;
            u32 a[3][4];
#pragma unroll
            for (int mi = 0; mi < 3; mi++) {
                u32 addr = a_base + (u32)(((wm + mi * 16 + (lane & 15)) * ASTRIDE +
                                            k0 + (lane >> 4) * 8) * 2);
                ldsm_x4(a[mi][0], a[mi][1], a[mi][2], a[mi][3], addr);
            }
            u32 b[2][2];
#pragma unroll
            for (int j = 0; j < 2; j++) {
                u32 addr = b_base + (u32)(((wn + j * 8 + (lane & 7)) * ASTRIDE +
                                            k0 + ((lane >> 3) & 1) * 8) * 2);
                ldsm_x2(b[j][0], b[j][1], addr);
            }
#pragma unroll
            for (int mi = 0; mi < 3; mi++)
#pragma unroll
                for (int j = 0; j < 2; j++)
                    mma16816(acc[mi][j], a[mi], b[j]);
        }
        __syncthreads();   // all warps done reading Bs

        // ---- prefetch B(cb+1) (lands during edge phase) ----
        if (cb < 63) {
            const char* Wsrc = (const char*)g_Wbf + (size_t)(cb + 1) * 128 * 384;
            for (int i = t; i < 128 * nq; i += 512) {
                int r = i / nq, q = i - r * nq;
                cpasync16(b_base + (u32)(r * 400 + q * 16),
                          Wsrc + (size_t)r * 384 + q * 16);
            }
        }
        cp_commit();

        // ---- write Qs (rows < NODE_G only) ----
#pragma unroll
        for (int mi = 0; mi < 3; mi++) {
            int m0 = wm + mi * 16 + (lane >> 2);
#pragma unroll
            for (int j = 0; j < 2; j++) {
                int col = wn + j * 8 + (lane & 3) * 2;
                if (m0 < NODE_G)
                    *(float2*)&Qs[m0 * QSTRIDE + col] = make_float2(acc[mi][j][0], acc[mi][j][1]);
                if (m0 + 8 < NODE_G)
                    *(float2*)&Qs[(m0 + 8) * QSTRIDE + col] = make_float2(acc[mi][j][2], acc[mi][j][3]);
            }
        }
        __syncthreads();   // Qs visible

        // ---- edge phase: 2 edges per warp iter, lane quad = 4 o's ----
        for (int pair = w; pair < npair; pair += 16) {
            int e = 2 * pair + eh;
            if (e < ceM) {
                int p = p0 + e;
                float2 h = *(const float2*)&g_H[(size_t)p * 128 + 2 * cb];
                int s = sl[e];
                float4 q0 = *(const float4*)&Qs[s * QSTRIDE + 4 * ol];
                float4 q1 = *(const float4*)&Qs[s * QSTRIDE + 64 + 4 * ol];
                float4 m = *(float4*)&macc[e * 64 + 4 * ol];
                m.x += h.x * q0.x + h.y * q1.x;
                m.y += h.x * q0.y + h.y * q1.y;
                m.z += h.x * q0.z + h.y * q1.z;
                m.w += h.x * q0.w + h.y * q1.w;
                *(float4*)&macc[e * 64 + 4 * ol] = m;
            }
        }
        // ---- overflow edges (rare): direct atomic per cb ----
        for (int e = ceM + w; e < ce; e += 16) {
            int p = p0 + e;
            float2 h = *(const float2*)&g_H[(size_t)p * 128 + 2 * cb];
            int sg = g_psrc[p];
            int s = sg - n0;
            int d = g_pdst[p];
            float2 q0 = *(const float2*)&Qs[s * QSTRIDE + 2 * lane];
            float2 q1 = *(const float2*)&Qs[s * QSTRIDE + 64 + 2 * lane];
            float ax = h.x * q0.x + h.y * q1.x;
            float ay = h.x * q0.y + h.y * q1.y;
            if (cb == 0) {
                ax += g_xb[(size_t)sg * 64 + 2 * lane];
                ay += g_xb[(size_t)sg * 64 + 2 * lane + 1];
            }
            atomicAdd(&g_agg[(size_t)d * 64 + 2 * lane], ax);
            atomicAdd(&g_agg[(size_t)d * 64 + 2 * lane + 1], ay);
        }
    }
    __syncthreads();

    // ---- flush macc: agg[dst] += macc + xb[src] ----
    for (int pair = w; pair < npair; pair += 16) {
        int e = 2 * pair + eh;
        if (e < ceM) {
            int p = p0 + e;
            int d = g_pdst[p];
            int sg = n0 + sl[e];
            float4 m = *(float4*)&macc[e * 64 + 4 * ol];
            float4 xv = *(const float4*)&g_xb[(size_t)sg * 64 + 4 * ol];
            atomicAdd(&g_agg[(size_t)d * 64 + 4 * ol],     m.x + xv.x);
            atomicAdd(&g_agg[(size_t)d * 64 + 4 * ol + 1], m.y + xv.y);
            atomicAdd(&g_agg[(size_t)d * 64 + 4 * ol + 2], m.z + xv.z);
            atomicAdd(&g_agg[(size_t)d * 64 + 4 * ol + 3], m.w + xv.w);
        }
    }
}

// ---------------- batch norm ----------------
__global__ void k_bn_zero() {
    int t = threadIdx.x;
    if (t < HID) { g_bnsum[t] = 0.f; g_bnsq[t] = 0.f; }
}
__global__ void k_bn_stats() {
    int t = threadIdx.x;
    int o = t & 63, s = t >> 6;
    float sum = 0.f, sq = 0.f;
    for (int n = blockIdx.x * 4 + s; n < NN; n += gridDim.x * 4) {
        float v = g_agg[(size_t)n * 64 + o];
        sum += v; sq += v * v;
    }
    __shared__ float ssum[256], ssq[256];
    ssum[t] = sum; ssq[t] = sq;
    __syncthreads();
    if (t < 128) { ssum[t] += ssum[t + 128]; ssq[t] += ssq[t + 128]; }
    __syncthreads();
    if (t < 64) {
        atomicAdd(&g_bnsum[t], ssum[t] + ssum[t + 64]);
        atomicAdd(&g_bnsq [t], ssq [t] + ssq [t + 64]);
    }
}
__global__ void k_bn_apply(const float* __restrict__ gamma,
                           const float* __restrict__ beta,
                           float* __restrict__ xout) {
    int i = blockIdx.x * blockDim.x + threadIdx.x;
    if (i >= NN * 64) return;
    int o = i & 63;
    float mu  = g_bnsum[o] * (1.f / NN);
    float var = g_bnsq[o] * (1.f / NN) - mu * mu;
    float v = gamma[o] * (g_agg[i] - mu) * rsqrtf(var + EPS_BN) + beta[o];
    xout[i] = fmaxf(v, 0.f);
}

// ---------------- pooling + final MLP ----------------
__global__ void k_pool_init() {
    int i = blockIdx.x * blockDim.x + threadIdx.x;
    if (i < NG * HID) g_pool[i] = 0.f;
}
__global__ void k_pool(const float* __restrict__ xl, const int* __restrict__ batch) {
    int i = blockIdx.x * blockDim.x + threadIdx.x;
    if (i >= NN * 64) return;
    int n = i >> 6, o = i & 63;
    int g = batch[n];
    atomicMax(reinterpret_cast<unsigned int*>(&g_pool[g * 64 + o]), __float_as_uint(xl[i]));
}
__global__ void k_final(const float* __restrict__ u,
                        const float* __restrict__ w1, const float* __restrict__ b1,
                        const float* __restrict__ w2, const float* __restrict__ b2,
                        float* __restrict__ out) {
    int g = blockIdx.x;
    int j = threadIdx.x;
    __shared__ float cat[72];
    __shared__ float red[64];
    if (j < 64) cat[j] = g_pool[g * 64 + j];
    if (j < 8)  cat[64 + j] = u[g * 8 + j];
    __syncthreads();
    float h = b1[j];
#pragma unroll
    for (int k = 0; k < 72; k++) h += cat[k] * w1[k * 64 + j];
    h = fmaxf(h, 0.f);
    red[j] = h * w2[j];
    __syncthreads();
    for (int s = 32; s > 0; s >>= 1) {
        if (j < s) red[j] += red[j + s];
        __syncthreads();
    }
    if (j == 0) out[g] = red[0] + b2[0];
}

// ---------------- host ----------------
extern "C" void kernel_launch(void* const* d_in, const int* in_sizes, int n_in,
                              void* d_out, int out_size) {
    const float* x       = (const float*)d_in[0];
    const int*   ei      = (const int*)  d_in[1];
    const float* ea      = (const float*)d_in[2];
    const int*   batch   = (const int*)  d_in[3];
    const float* u       = (const float*)d_in[4];
    const float* enn0_w1 = (const float*)d_in[5];
    const float* enn0_b1 = (const float*)d_in[6];
    const float* enn0_w2 = (const float*)d_in[7];
    const float* enn0_b2 = (const float*)d_in[8];
    const float* root0   = (const float*)d_in[9];
    const float* bias0   = (const float*)d_in[10];
    const float* gamma0  = (const float*)d_in[11];
    const float* beta0   = (const float*)d_in[12];
    const float* enn_w1  = (const float*)d_in[13];
    const float* enn_b1  = (const float*)d_in[14];
    const float* enn_w2  = (const float*)d_in[15];
    const float* enn_b2  = (const float*)d_in[16];
    const float* root_l  = (const float*)d_in[17];
    const float* bias_l  = (const float*)d_in[18];
    const float* gamma_l = (const float*)d_in[19];
    const float* beta_l  = (const float*)d_in[20];
    const float* pp_w1   = (const float*)d_in[21];
    const float* pp_b1   = (const float*)d_in[22];
    const float* pp_w2   = (const float*)d_in[23];
    const float* pp_b2   = (const float*)d_in[24];

    const int* src  = ei;
    const int* dste = ei + NE;

    cudaFuncSetAttribute(k_fused, cudaFuncAttributeMaxDynamicSharedMemorySize, FO_TOTAL);

    void* pA; cudaGetSymbolAddress(&pA, g_xA);
    void* pB; cudaGetSymbolAddress(&pB, g_xB);
    float* xA = (float*)pA;
    float* xB = (float*)pB;

    k_zero_cnt<<<(NN + 255) / 256, 256>>>();
    k_count  <<<(NE + 255) / 256, 256>>>(src);
    k_scan   <<<1, 1024>>>();
    k_scatter<<<(NE + 255) / 256, 256>>>(src, dste);

    const float* xin = x;
    int C = IN_CH;
    float* xout = xA;

    for (int l = 0; l < 4; l++) {
        const float *w1, *b1, *w2, *b2, *rt, *bs, *gm, *bt;
        if (l == 0) {
            w1 = enn0_w1; b1 = enn0_b1; w2 = enn0_w2; b2 = enn0_b2;
            rt = root0; bs = bias0; gm = gamma0; bt = beta0;
        } else {
            int m = l - 1;
            w1 = enn_w1 + (size_t)m * EIN * 128;
            b1 = enn_b1 + (size_t)m * 128;
            w2 = enn_w2 + (size_t)m * 128 * 4096;
            b2 = enn_b2 + (size_t)m * 4096;
            rt = root_l + (size_t)m * 64 * 64;
            bs = bias_l + (size_t)m * 64;
            gm = gamma_l + (size_t)m * 64;
            bt = beta_l + (size_t)m * 64;
        }
        k_wsplit2 <<<128, 256>>>(w2, C);
        k_edge_h  <<<(NE + EPC - 1) / EPC, 128>>>(ea, w1, b1);
        k_node_pre<<<(NN + 3) / 4, 256>>>(xin, C, rt, bs, b2);
        k_fused   <<<148, 512, FO_TOTAL>>>(xin, C);
        k_bn_zero <<<1, 64>>>();
        k_bn_stats<<<128, 256>>>();
        k_bn_apply<<<(NN * 64 + 255) / 256, 256>>>(gm, bt, xout);

        xin = xout;
        C = HID;
        xout = (xout == xA) ? xB : xA;
    }

    k_pool_init<<<(NG * HID + 255) / 256, 256>>>();
    k_pool     <<<(NN * 64 + 255) / 256, 256>>>(xin, batch);
    k_final    <<<NG, 64>>>(u, pp_w1, pp_b1, pp_w2, pp_b2, (float*)d_out);
}